// round 11
// baseline (speedup 1.0000x reference)
#include <cuda_runtime.h>
#include <cuda_fp16.h>
#include <cstdint>

#define NN    4096
#define DD    128
#define TWO_N 8192
#define ZC    256
#define KSPLIT 4
#define KPER  (NN / KSPLIT)      // 1024 per CTA
#define KC    64
#define NCHC  (KPER / KC)        // 16 chunks per CTA
#define NCH_ALL (NN / KC)        // 64 chunks total
#define BSTG  16384              // B stage: 64x128 fp16
#define STG   17408              // B + 1KB mask
#define SMEM_GEMM (3 * STG)      // 52224 -> 2 CTAs/SM

// ------------------------- device scratch -------------------------
__device__ __align__(16) unsigned g_maskT[(size_t)NCH_ALL * NN * 2]; // 2 MB [chunk][row][2w]
__device__ __align__(16) __half g_Zh[(size_t)NN * ZC];               // 2 MB [K][N]
__device__ __align__(16) float g_XW[(size_t)TWO_N * DD];             // 4 MB
__device__ __align__(16) float g_Yp[KSPLIT][(size_t)NN * ZC];        // 16 MB partials
__device__ float g_s[NN];
__device__ float g_stats[2 * DD];

// ------------------------- PTX helpers ----------------------------
__device__ __forceinline__ uint32_t smem_u32(const void* p) {
    uint32_t a;
    asm("{ .reg .u64 t; cvta.to.shared.u64 t, %1; cvt.u32.u64 %0, t; }" : "=r"(a) : "l"(p));
    return a;
}
#define CP16(dst, src) asm volatile("cp.async.cg.shared.global [%0], [%1], 16;" :: "r"(dst), "l"(src))
#define CP8(dst, src)  asm volatile("cp.async.ca.shared.global [%0], [%1], 8;"  :: "r"(dst), "l"(src))
#define CP_COMMIT()    asm volatile("cp.async.commit_group;" ::: "memory")
#define CP_WAIT1()     asm volatile("cp.async.wait_group 1;" ::: "memory")

#define LDSM4T(r, a) asm volatile("ldmatrix.sync.aligned.m8n8.x4.trans.shared.b16 {%0,%1,%2,%3}, [%4];" \
    : "=r"((r)[0]),"=r"((r)[1]),"=r"((r)[2]),"=r"((r)[3]) : "r"(a))

#define MMA(d, a, b0_, b1_) asm volatile( \
    "mma.sync.aligned.m16n8k16.row.col.f32.f16.f16.f32 " \
    "{%0,%1,%2,%3},{%4,%5,%6,%7},{%8,%9},{%0,%1,%2,%3};" \
    : "+f"((d)[0]),"+f"((d)[1]),"+f"((d)[2]),"+f"((d)[3]) \
    : "r"((a)[0]),"r"((a)[1]),"r"((a)[2]),"r"((a)[3]), "r"(b0_), "r"(b1_))

// 2 bits -> packed fp16x2 (bit0 -> low half, bit1 -> high half), 1.0 or 0.0
__device__ __forceinline__ uint32_t lut2(unsigned e) {
    return ((e & 1u) ? 0x3C00u : 0u) | ((e & 2u) ? 0x3C000000u : 0u);
}

// ---------------------------------------------------------------------------
// K1: binarize A -> transposed bitmask [chunk][row][2 words]; rowsum -> s.
// ---------------------------------------------------------------------------
__global__ void k_prep(const float* __restrict__ A) {
    int row = blockIdx.x, t = threadIdx.x, w = t >> 5, l = t & 31;
    __shared__ int scnt[4];
    if (row == 0 && t < 128) { g_stats[t] = 0.0f; g_stats[128 + t] = 0.0f; }
    const float* ar = A + (size_t)row * NN;
    int cnt = 0;
    #pragma unroll 4
    for (int it = 0; it < 32; ++it) {
        float v = ar[it * 128 + t];
        bool b = (v > 0.0f);
        unsigned bal = __ballot_sync(0xffffffffu, b);
        cnt += b ? 1 : 0;
        if (l == 0) {
            int W = it * 4 + w;                      // 32-col word index 0..127
            g_maskT[((size_t)(W >> 1) * NN + row) * 2 + (W & 1)] = bal;
        }
    }
    #pragma unroll
    for (int o = 16; o; o >>= 1) cnt += __shfl_down_sync(0xffffffffu, cnt, o);
    if (l == 0) scnt[w] = cnt;
    __syncthreads();
    if (t == 0)
        g_s[row] = rsqrtf((float)(scnt[0] + scnt[1] + scnt[2] + scnt[3] + 1));
}

// ---------------------------------------------------------------------------
// K2: fused xw = x@W and Z build (fp16 rows).
// ---------------------------------------------------------------------------
__global__ void k_xw2(const float* __restrict__ x, const float* __restrict__ W) {
    __shared__ float xs[64][128];
    int t = threadIdx.x, w = t >> 5, l = t & 31;
    int j0 = blockIdx.x * 32;
    const float4* xt = (const float4*)(x + (size_t)j0 * DD);
    const float4* xb = (const float4*)(x + (size_t)(NN + j0) * DD);
    float4* xs4 = (float4*)xs;
    #pragma unroll
    for (int i = 0; i < 4; ++i) xs4[t + i * 256] = xt[t + i * 256];
    #pragma unroll
    for (int i = 0; i < 4; ++i) xs4[1024 + t + i * 256] = xb[t + i * 256];
    __syncthreads();
    const float4* W4 = (const float4*)W;
    float acc[8][4];
    #pragma unroll
    for (int i = 0; i < 8; ++i) { acc[i][0]=0.f; acc[i][1]=0.f; acc[i][2]=0.f; acc[i][3]=0.f; }
    #pragma unroll 4
    for (int k = 0; k < DD; ++k) {
        float4 wv = W4[k * 32 + l];
        #pragma unroll
        for (int i = 0; i < 8; ++i) {
            float u = xs[w * 8 + i][k];
            acc[i][0] += u * wv.x; acc[i][1] += u * wv.y;
            acc[i][2] += u * wv.z; acc[i][3] += u * wv.w;
        }
    }
    #pragma unroll
    for (int i = 0; i < 8; ++i) {
        int r = w * 8 + i;
        int top = (r < 32);
        int j = j0 + (r & 31);
        int grow = top ? j : (NN + j);
        float4 v = make_float4(acc[i][0], acc[i][1], acc[i][2], acc[i][3]);
        *(float4*)&g_XW[(size_t)grow * DD + 4 * l] = v;
        float s = g_s[j];
        __half h0 = __float2half_rn(s * v.x);
        __half h1 = __float2half_rn(s * v.y);
        __half h2 = __float2half_rn(s * v.z);
        __half h3 = __float2half_rn(s * v.w);
        uint2 hp;
        hp.x = (unsigned)__half_as_ushort(h0) | ((unsigned)__half_as_ushort(h1) << 16);
        hp.y = (unsigned)__half_as_ushort(h2) | ((unsigned)__half_as_ushort(h3) << 16);
        int coff = (top ? 0 : DD) + 4 * l;
        *(uint2*)&g_Zh[(size_t)j * ZC + coff] = hp;
    }
}

// ---------------------------------------------------------------------------
// K3: GEMM partials. grid (32, 2, 4): CTA 128x128, K-split/4 on grid.z.
// 256 threads, 8 warps: 4 M-groups x 2 N-halves, warp tile 32x64.
// B smem traffic 64KB/CTA/chunk (1024 cyc/SM < 1792 cyc MMA) -> MMA-bound.
// A expanded from bitmask in registers. 3-stage cp.async, one barrier
// per chunk, 2 CTAs/SM -> 4 warps/SMSP.
// ---------------------------------------------------------------------------
__global__ void __launch_bounds__(256, 2) k_gemm() {
    extern __shared__ char smem[];
    uint32_t sb = smem_u32(smem);
    int t = threadIdx.x, wid = t >> 5, lid = t & 31;
    int wm = wid & 3, wn = wid >> 2;
    int m0 = wm * 32, nb0 = wn * 64;
    int mbase = blockIdx.x * 128;
    int nbg   = blockIdx.y * 128;
    const __half* Bg = g_Zh + (size_t)(blockIdx.z * KPER) * ZC + nbg;
    const unsigned* Mg = g_maskT + ((size_t)(blockIdx.z * NCHC) * NN + mbase) * 2;

    auto issue = [&](int c) {
        if (c < NCHC) {
            uint32_t sa = sb + (c % 3) * STG;
            #pragma unroll
            for (int p = 0; p < 4; ++p) {            // B: 64x128 fp16, 256B rows
                int idx = t + p * 256;
                int k = idx >> 4, ch = idx & 15;
                uint32_t off = k * 256 + ((ch ^ (k & 7)) << 4);
                CP16(sa + off, (const char*)(Bg + (size_t)(c * KC + k) * ZC + ch * 8));
            }
            if (t < 128)                              // mask: 128 rows x 8B
                CP8(sa + BSTG + t * 8, (const char*)(Mg + (size_t)c * NN * 2 + t * 2));
        }
        CP_COMMIT();
    };

    float acc[2][8][4];
    #pragma unroll
    for (int mi = 0; mi < 2; ++mi)
        #pragma unroll
        for (int nj = 0; nj < 8; ++nj)
            #pragma unroll
            for (int q = 0; q < 4; ++q) acc[mi][nj][q] = 0.0f;

    issue(0); issue(1);

    int ra = lid >> 2;
    int c0 = (lid & 3) * 2;

    for (int c = 0; c < NCHC; ++c) {
        CP_WAIT1();                  // chunk c resident
        __syncthreads();             // all warps done with stage (c-1)%3
        issue(c + 2);                // refills stage (c+2)%3 == (c-1)%3
        uint32_t sa = sb + (c % 3) * STG;
        const uint2* maskS = (const uint2*)(smem + (c % 3) * STG + BSTG);

        uint2 mwA0 = maskS[m0 + ra];          // mi=0: rows m0+ra, m0+ra+8
        uint2 mwA1 = maskS[m0 + ra + 8];
        uint2 mwB0 = maskS[m0 + 16 + ra];     // mi=1
        uint2 mwB1 = maskS[m0 + 16 + ra + 8];

        #pragma unroll
        for (int kk = 0; kk < 4; ++kk) {
            int kb = kk * 16 + (lid & 15);
            int cb = lid >> 4;
            int sh = ((kk & 1) << 4) + c0;
            uint32_t af[2][4];
            {
                unsigned ta = ((kk < 2) ? mwA0.x : mwA0.y) >> sh;
                unsigned tb = ((kk < 2) ? mwA1.x : mwA1.y) >> sh;
                af[0][0] = lut2(ta & 3u);
                af[0][1] = lut2(tb & 3u);
                af[0][2] = lut2((ta >> 8) & 3u);
                af[0][3] = lut2((tb >> 8) & 3u);
            }
            {
                unsigned ta = ((kk < 2) ? mwB0.x : mwB0.y) >> sh;
                unsigned tb = ((kk < 2) ? mwB1.x : mwB1.y) >> sh;
                af[1][0] = lut2(ta & 3u);
                af[1][1] = lut2(tb & 3u);
                af[1][2] = lut2((ta >> 8) & 3u);
                af[1][3] = lut2((tb >> 8) & 3u);
            }
            uint32_t bf[8][2];
            #pragma unroll
            for (int np = 0; np < 4; ++np) {         // 4 LDSM -> 64 cols
                int ch = (nb0 >> 3) + np * 2 + cb;
                uint32_t r4[4];
                LDSM4T(r4, sa + kb * 256 + ((ch ^ (kb & 7)) << 4));
                bf[np*2][0]=r4[0]; bf[np*2][1]=r4[1];
                bf[np*2+1][0]=r4[2]; bf[np*2+1][1]=r4[3];
            }
            #pragma unroll
            for (int mi = 0; mi < 2; ++mi)
                #pragma unroll
                for (int nj = 0; nj < 8; ++nj)
                    MMA(acc[mi][nj], af[mi], bf[nj][0], bf[nj][1]);
        }
    }

    // write partial tile (32 rows x 64 cols per warp)
    float* Yp = g_Yp[blockIdx.z];
    int grp = lid >> 2, qp = lid & 3;
    #pragma unroll
    for (int mi = 0; mi < 2; ++mi) {
        int r0 = mbase + m0 + mi * 16 + grp;
        int r1 = r0 + 8;
        #pragma unroll
        for (int nj = 0; nj < 8; ++nj) {
            int cc = nbg + nb0 + nj * 8 + qp * 2;
            *(float2*)&Yp[(size_t)r0 * ZC + cc] = make_float2(acc[mi][nj][0], acc[mi][nj][1]);
            *(float2*)&Yp[(size_t)r1 * ZC + cc] = make_float2(acc[mi][nj][2], acc[mi][nj][3]);
        }
    }
}

// ---------------------------------------------------------------------------
// K4: epilogue. Sum partials, s-scale + diag, write out, BN stats.
// grid 128 x 256, 8 slots/thread (column-invariant striding, high MLP).
// ---------------------------------------------------------------------------
__global__ void k_epi(float* __restrict__ out) {
    __shared__ float sstat[2 * DD];
    int t = threadIdx.x;
    sstat[t] = 0.0f;
    __syncthreads();
    int base = blockIdx.x * 256 + t;            // 8 slots/thread, stride 32768
    int C = (base & 63) * 4;                    // column invariant across slots
    float lsum[4] = {0.f, 0.f, 0.f, 0.f};
    float lsq[4]  = {0.f, 0.f, 0.f, 0.f};
    int oc = (C < DD) ? C : (C - DD);
    #pragma unroll
    for (int sIt = 0; sIt < 8; ++sIt) {
        int slot = base + sIt * 32768;
        int i = slot >> 6;
        float4 y = *(const float4*)&g_Yp[0][(size_t)i * ZC + C];
        #pragma unroll
        for (int z = 1; z < KSPLIT; ++z) {
            float4 p = *(const float4*)&g_Yp[z][(size_t)i * ZC + C];
            y.x += p.x; y.y += p.y; y.z += p.z; y.w += p.w;
        }
        float s = g_s[i], s2 = s * s;
        int orow, drow;
        if (C < DD) { orow = i; drow = NN + i; }
        else        { orow = NN + i; drow = i; }
        float4 d = *(const float4*)&g_XW[(size_t)drow * DD + oc];
        float4 h;
        h.x = s * y.x + s2 * d.x; h.y = s * y.y + s2 * d.y;
        h.z = s * y.z + s2 * d.z; h.w = s * y.w + s2 * d.w;
        *(float4*)&out[(size_t)orow * DD + oc] = h;
        lsum[0] += h.x; lsum[1] += h.y; lsum[2] += h.z; lsum[3] += h.w;
        lsq[0] += h.x * h.x; lsq[1] += h.y * h.y; lsq[2] += h.z * h.z; lsq[3] += h.w * h.w;
    }
    #pragma unroll
    for (int q = 0; q < 4; ++q) {
        atomicAdd(&sstat[oc + q], lsum[q]);
        atomicAdd(&sstat[DD + oc + q], lsq[q]);
    }
    __syncthreads();
    atomicAdd(&g_stats[t], sstat[t]);
}

// ---------------------------------------------------------------------------
// K5: finalize BatchNorm (biased var) + ReLU in place, float4/thread.
// ---------------------------------------------------------------------------
__global__ void k_bn(float* __restrict__ out,
                     const float* __restrict__ gamma,
                     const float* __restrict__ beta) {
    __shared__ float sscale[DD], sshift[DD];
    int t = threadIdx.x;
    if (t < DD) {
        float mean = g_stats[t] * (1.0f / (float)TWO_N);
        float var  = g_stats[DD + t] * (1.0f / (float)TWO_N) - mean * mean;
        float inv  = rsqrtf(var + 1e-5f);
        float g = gamma[t];
        sscale[t] = inv * g;
        sshift[t] = beta[t] - mean * inv * g;
    }
    __syncthreads();
    int idx = (blockIdx.x * 256 + t) * 4;
    int c = idx & (DD - 1);
    float4 v = *(float4*)&out[idx];
    v.x = fmaxf(v.x * sscale[c]     + sshift[c],     0.0f);
    v.y = fmaxf(v.y * sscale[c + 1] + sshift[c + 1], 0.0f);
    v.z = fmaxf(v.z * sscale[c + 2] + sshift[c + 2], 0.0f);
    v.w = fmaxf(v.w * sscale[c + 3] + sshift[c + 3], 0.0f);
    *(float4*)&out[idx] = v;
}

// ---------------------------------------------------------------------------
extern "C" void kernel_launch(void* const* d_in, const int* in_sizes, int n_in,
                              void* d_out, int out_size) {
    const float* x     = (const float*)d_in[0];   // [8192, 128]
    const float* A     = (const float*)d_in[1];   // [4096, 4096]
    const float* Wm    = (const float*)d_in[2];   // [128, 128]
    const float* gamma = (const float*)d_in[3];   // [128]
    const float* beta  = (const float*)d_in[4];   // [128]
    float* out = (float*)d_out;                   // [8192, 128]

    cudaFuncSetAttribute(k_gemm, cudaFuncAttributeMaxDynamicSharedMemorySize, SMEM_GEMM);

    k_prep<<<NN, 128>>>(A);
    k_xw2 <<<NN / 32, 256>>>(x, Wm);
    dim3 gg(NN / 128, 2, KSPLIT);
    k_gemm<<<gg, 256, SMEM_GEMM>>>();
    k_epi <<<128, 256>>>(out);
    k_bn  <<<(TWO_N * DD) / 1024, 256>>>(out, gamma, beta);
}

// round 12
// speedup vs baseline: 1.1171x; 1.1171x over previous
#include <cuda_runtime.h>
#include <cuda_fp16.h>
#include <cstdint>

#define NN    4096
#define DD    128
#define TWO_N 8192
#define ZC    256
#define KSPLIT 4
#define KPER  (NN / KSPLIT)      // 1024 per CTA
#define KC    64
#define NCHC  (KPER / KC)        // 16 chunks per CTA
#define NCH_ALL (NN / KC)        // 64 chunks total
#define BSTG  16384              // B stage: 64x128 fp16
#define STG   17408              // B + 1KB mask
#define SMEM_GEMM (3 * STG)      // 52224 -> 2 CTAs/SM

// ------------------------- device scratch -------------------------
__device__ __align__(16) unsigned g_maskT[(size_t)NCH_ALL * NN * 2]; // 2 MB [chunk][row][2w]
__device__ __align__(16) __half g_Zh[(size_t)NN * ZC];               // 2 MB [K][N]
__device__ __align__(16) float g_XW[(size_t)TWO_N * DD];             // 4 MB
__device__ __align__(16) float g_Yp[KSPLIT][(size_t)NN * ZC];        // 16 MB partials
__device__ float g_s[NN];
__device__ float g_stats[2 * DD];

// ------------------------- PTX helpers ----------------------------
__device__ __forceinline__ uint32_t smem_u32(const void* p) {
    uint32_t a;
    asm("{ .reg .u64 t; cvta.to.shared.u64 t, %1; cvt.u32.u64 %0, t; }" : "=r"(a) : "l"(p));
    return a;
}
#define CP16(dst, src) asm volatile("cp.async.cg.shared.global [%0], [%1], 16;" :: "r"(dst), "l"(src))
#define CP8(dst, src)  asm volatile("cp.async.ca.shared.global [%0], [%1], 8;"  :: "r"(dst), "l"(src))
#define CP_COMMIT()    asm volatile("cp.async.commit_group;" ::: "memory")
#define CP_WAIT1()     asm volatile("cp.async.wait_group 1;" ::: "memory")

#define LDSM4T(r, a) asm volatile("ldmatrix.sync.aligned.m8n8.x4.trans.shared.b16 {%0,%1,%2,%3}, [%4];" \
    : "=r"((r)[0]),"=r"((r)[1]),"=r"((r)[2]),"=r"((r)[3]) : "r"(a))

#define MMA(d, a, b0_, b1_) asm volatile( \
    "mma.sync.aligned.m16n8k16.row.col.f32.f16.f16.f32 " \
    "{%0,%1,%2,%3},{%4,%5,%6,%7},{%8,%9},{%0,%1,%2,%3};" \
    : "+f"((d)[0]),"+f"((d)[1]),"+f"((d)[2]),"+f"((d)[3]) \
    : "r"((a)[0]),"r"((a)[1]),"r"((a)[2]),"r"((a)[3]), "r"(b0_), "r"(b1_))

// 2 bits -> packed fp16x2 (bit0 -> low half, bit1 -> high half), 1.0 or 0.0
__device__ __forceinline__ uint32_t lut2(unsigned e) {
    return ((e & 1u) ? 0x3C00u : 0u) | ((e & 2u) ? 0x3C000000u : 0u);
}

// ---------------------------------------------------------------------------
// K1: binarize A -> transposed bitmask [chunk][row][2 words]; rowsum -> s.
// ---------------------------------------------------------------------------
__global__ void k_prep(const float* __restrict__ A) {
    int row = blockIdx.x, t = threadIdx.x, w = t >> 5, l = t & 31;
    __shared__ int scnt[4];
    if (row == 0 && t < 128) { g_stats[t] = 0.0f; g_stats[128 + t] = 0.0f; }
    const float* ar = A + (size_t)row * NN;
    int cnt = 0;
    #pragma unroll 4
    for (int it = 0; it < 32; ++it) {
        float v = ar[it * 128 + t];
        bool b = (v > 0.0f);
        unsigned bal = __ballot_sync(0xffffffffu, b);
        cnt += b ? 1 : 0;
        if (l == 0) {
            int W = it * 4 + w;                      // 32-col word index 0..127
            g_maskT[((size_t)(W >> 1) * NN + row) * 2 + (W & 1)] = bal;
        }
    }
    #pragma unroll
    for (int o = 16; o; o >>= 1) cnt += __shfl_down_sync(0xffffffffu, cnt, o);
    if (l == 0) scnt[w] = cnt;
    __syncthreads();
    if (t == 0)
        g_s[row] = rsqrtf((float)(scnt[0] + scnt[1] + scnt[2] + scnt[3] + 1));
}

// ---------------------------------------------------------------------------
// K2: fused xw = x@W and Z build (fp16 rows).
// ---------------------------------------------------------------------------
__global__ void k_xw2(const float* __restrict__ x, const float* __restrict__ W) {
    __shared__ float xs[64][128];
    int t = threadIdx.x, w = t >> 5, l = t & 31;
    int j0 = blockIdx.x * 32;
    const float4* xt = (const float4*)(x + (size_t)j0 * DD);
    const float4* xb = (const float4*)(x + (size_t)(NN + j0) * DD);
    float4* xs4 = (float4*)xs;
    #pragma unroll
    for (int i = 0; i < 4; ++i) xs4[t + i * 256] = xt[t + i * 256];
    #pragma unroll
    for (int i = 0; i < 4; ++i) xs4[1024 + t + i * 256] = xb[t + i * 256];
    __syncthreads();
    const float4* W4 = (const float4*)W;
    float acc[8][4];
    #pragma unroll
    for (int i = 0; i < 8; ++i) { acc[i][0]=0.f; acc[i][1]=0.f; acc[i][2]=0.f; acc[i][3]=0.f; }
    #pragma unroll 4
    for (int k = 0; k < DD; ++k) {
        float4 wv = W4[k * 32 + l];
        #pragma unroll
        for (int i = 0; i < 8; ++i) {
            float u = xs[w * 8 + i][k];
            acc[i][0] += u * wv.x; acc[i][1] += u * wv.y;
            acc[i][2] += u * wv.z; acc[i][3] += u * wv.w;
        }
    }
    #pragma unroll
    for (int i = 0; i < 8; ++i) {
        int r = w * 8 + i;
        int top = (r < 32);
        int j = j0 + (r & 31);
        int grow = top ? j : (NN + j);
        float4 v = make_float4(acc[i][0], acc[i][1], acc[i][2], acc[i][3]);
        *(float4*)&g_XW[(size_t)grow * DD + 4 * l] = v;
        float s = g_s[j];
        __half h0 = __float2half_rn(s * v.x);
        __half h1 = __float2half_rn(s * v.y);
        __half h2 = __float2half_rn(s * v.z);
        __half h3 = __float2half_rn(s * v.w);
        uint2 hp;
        hp.x = (unsigned)__half_as_ushort(h0) | ((unsigned)__half_as_ushort(h1) << 16);
        hp.y = (unsigned)__half_as_ushort(h2) | ((unsigned)__half_as_ushort(h3) << 16);
        int coff = (top ? 0 : DD) + 4 * l;
        *(uint2*)&g_Zh[(size_t)j * ZC + coff] = hp;
    }
}

// ---------------------------------------------------------------------------
// K3: GEMM partials (round-10 proven config). grid (32, 2, 4): CTA 128x128,
// K-split/4 on grid.z. 8 warps, warp tile 16x128 (one mask expansion per kk
// feeds 16 MMAs). 3-stage cp.async, one barrier per chunk, 2 CTAs/SM.
// ---------------------------------------------------------------------------
__global__ void __launch_bounds__(256, 2) k_gemm() {
    extern __shared__ char smem[];
    uint32_t sb = smem_u32(smem);
    int t = threadIdx.x, wid = t >> 5, lid = t & 31;
    int m0 = wid * 16;
    int mbase = blockIdx.x * 128;
    int nbg   = blockIdx.y * 128;
    const __half* Bg = g_Zh + (size_t)(blockIdx.z * KPER) * ZC + nbg;
    const unsigned* Mg = g_maskT + ((size_t)(blockIdx.z * NCHC) * NN + mbase) * 2;

    auto issue = [&](int c) {
        if (c < NCHC) {
            uint32_t sa = sb + (c % 3) * STG;
            #pragma unroll
            for (int p = 0; p < 4; ++p) {            // B: 64x128 fp16, 256B rows
                int idx = t + p * 256;
                int k = idx >> 4, ch = idx & 15;
                uint32_t off = k * 256 + ((ch ^ (k & 7)) << 4);
                CP16(sa + off, (const char*)(Bg + (size_t)(c * KC + k) * ZC + ch * 8));
            }
            if (t < 128)                              // mask: 128 rows x 8B
                CP8(sa + BSTG + t * 8, (const char*)(Mg + (size_t)c * NN * 2 + t * 2));
        }
        CP_COMMIT();
    };

    float acc[16][4];
    #pragma unroll
    for (int nj = 0; nj < 16; ++nj)
        #pragma unroll
        for (int q = 0; q < 4; ++q) acc[nj][q] = 0.0f;

    issue(0); issue(1);

    int ra = lid >> 2;
    int c0 = (lid & 3) * 2;

    for (int c = 0; c < NCHC; ++c) {
        CP_WAIT1();                  // chunk c resident
        __syncthreads();             // all warps done with stage (c-1)%3
        issue(c + 2);                // refills stage (c+2)%3 == (c-1)%3
        uint32_t sa = sb + (c % 3) * STG;
        const uint2* maskS = (const uint2*)(smem + (c % 3) * STG + BSTG);

        uint2 mw0 = maskS[m0 + ra];      // row m0+ra of my strip
        uint2 mw1 = maskS[m0 + ra + 8];  // row m0+ra+8

        #pragma unroll
        for (int kk = 0; kk < 4; ++kk) {
            int kb = kk * 16 + (lid & 15);
            int cb = lid >> 4;
            int sh = ((kk & 1) << 4) + c0;
            unsigned ta = ((kk < 2) ? mw0.x : mw0.y) >> sh;
            unsigned tb = ((kk < 2) ? mw1.x : mw1.y) >> sh;
            uint32_t af[4];
            af[0] = lut2(ta & 3u);           // (ra,   c0..c0+1)
            af[1] = lut2(tb & 3u);           // (ra+8, c0..c0+1)
            af[2] = lut2((ta >> 8) & 3u);    // (ra,   c0+8..c0+9)
            af[3] = lut2((tb >> 8) & 3u);    // (ra+8, c0+8..c0+9)
            #pragma unroll
            for (int g = 0; g < 4; ++g) {            // 4 groups of 32 cols
                uint32_t bf[4][2];
                #pragma unroll
                for (int np = 0; np < 2; ++np) {
                    int ch = g * 4 + np * 2 + cb;    // 16B column-chunk index
                    uint32_t r4[4];
                    LDSM4T(r4, sa + kb * 256 + ((ch ^ (kb & 7)) << 4));
                    bf[np*2][0]=r4[0]; bf[np*2][1]=r4[1];
                    bf[np*2+1][0]=r4[2]; bf[np*2+1][1]=r4[3];
                }
                #pragma unroll
                for (int nj = 0; nj < 4; ++nj)
                    MMA(acc[g * 4 + nj], af, bf[nj][0], bf[nj][1]);
            }
        }
    }

    // write partial tile (16 rows x 128 cols per warp)
    float* Yp = g_Yp[blockIdx.z];
    int grp = lid >> 2, qp = lid & 3;
    int r0 = mbase + m0 + grp;
    int r1 = r0 + 8;
    #pragma unroll
    for (int nj = 0; nj < 16; ++nj) {
        int cc = nbg + nj * 8 + qp * 2;
        *(float2*)&Yp[(size_t)r0 * ZC + cc] = make_float2(acc[nj][0], acc[nj][1]);
        *(float2*)&Yp[(size_t)r1 * ZC + cc] = make_float2(acc[nj][2], acc[nj][3]);
    }
}

// ---------------------------------------------------------------------------
// K4: epilogue (round-10 proven config). grid 256 x 256, 4 slots/thread.
// ---------------------------------------------------------------------------
__global__ void k_epi(float* __restrict__ out) {
    __shared__ float sstat[2 * DD];
    int t = threadIdx.x;
    sstat[t] = 0.0f;
    __syncthreads();
    int base = blockIdx.x * 256 + t;            // 4 slots/thread, stride 65536
    int C = (base & 63) * 4;                    // column invariant across slots
    float lsum[4] = {0.f, 0.f, 0.f, 0.f};
    float lsq[4]  = {0.f, 0.f, 0.f, 0.f};
    int oc = (C < DD) ? C : (C - DD);
    #pragma unroll
    for (int sIt = 0; sIt < 4; ++sIt) {
        int slot = base + sIt * 65536;
        int i = slot >> 6;
        float4 y = *(const float4*)&g_Yp[0][(size_t)i * ZC + C];
        #pragma unroll
        for (int z = 1; z < KSPLIT; ++z) {
            float4 p = *(const float4*)&g_Yp[z][(size_t)i * ZC + C];
            y.x += p.x; y.y += p.y; y.z += p.z; y.w += p.w;
        }
        float s = g_s[i], s2 = s * s;
        int orow, drow;
        if (C < DD) { orow = i; drow = NN + i; }
        else        { orow = NN + i; drow = i; }
        float4 d = *(const float4*)&g_XW[(size_t)drow * DD + oc];
        float4 h;
        h.x = s * y.x + s2 * d.x; h.y = s * y.y + s2 * d.y;
        h.z = s * y.z + s2 * d.z; h.w = s * y.w + s2 * d.w;
        *(float4*)&out[(size_t)orow * DD + oc] = h;
        lsum[0] += h.x; lsum[1] += h.y; lsum[2] += h.z; lsum[3] += h.w;
        lsq[0] += h.x * h.x; lsq[1] += h.y * h.y; lsq[2] += h.z * h.z; lsq[3] += h.w * h.w;
    }
    #pragma unroll
    for (int q = 0; q < 4; ++q) {
        atomicAdd(&sstat[oc + q], lsum[q]);
        atomicAdd(&sstat[DD + oc + q], lsq[q]);
    }
    __syncthreads();
    atomicAdd(&g_stats[t], sstat[t]);
}

// ---------------------------------------------------------------------------
// K5: finalize BatchNorm (biased var) + ReLU, float4 per thread.
// ---------------------------------------------------------------------------
__global__ void k_bn(float* __restrict__ out,
                     const float* __restrict__ gamma,
                     const float* __restrict__ beta) {
    __shared__ float sscale[DD], sshift[DD];
    int t = threadIdx.x;
    if (t < DD) {
        float mean = g_stats[t] * (1.0f / (float)TWO_N);
        float var  = g_stats[DD + t] * (1.0f / (float)TWO_N) - mean * mean;
        float inv  = rsqrtf(var + 1e-5f);
        float g = gamma[t];
        sscale[t] = inv * g;
        sshift[t] = beta[t] - mean * inv * g;
    }
    __syncthreads();
    int idx = (blockIdx.x * 256 + t) * 4;
    int c = idx & (DD - 1);
    float4 v = *(float4*)&out[idx];
    v.x = fmaxf(v.x * sscale[c]     + sshift[c],     0.0f);
    v.y = fmaxf(v.y * sscale[c + 1] + sshift[c + 1], 0.0f);
    v.z = fmaxf(v.z * sscale[c + 2] + sshift[c + 2], 0.0f);
    v.w = fmaxf(v.w * sscale[c + 3] + sshift[c + 3], 0.0f);
    *(float4*)&out[idx] = v;
}

// ---------------------------------------------------------------------------
extern "C" void kernel_launch(void* const* d_in, const int* in_sizes, int n_in,
                              void* d_out, int out_size) {
    const float* x     = (const float*)d_in[0];   // [8192, 128]
    const float* A     = (const float*)d_in[1];   // [4096, 4096]
    const float* Wm    = (const float*)d_in[2];   // [128, 128]
    const float* gamma = (const float*)d_in[3];   // [128]
    const float* beta  = (const float*)d_in[4];   // [128]
    float* out = (float*)d_out;                   // [8192, 128]

    cudaFuncSetAttribute(k_gemm, cudaFuncAttributeMaxDynamicSharedMemorySize, SMEM_GEMM);

    k_prep<<<NN, 128>>>(A);
    k_xw2 <<<NN / 32, 256>>>(x, Wm);
    dim3 gg(NN / 128, 2, KSPLIT);
    k_gemm<<<gg, 256, SMEM_GEMM>>>();
    k_epi <<<256, 256>>>(out);
    k_bn  <<<(TWO_N * DD) / 1024, 256>>>(out, gamma, beta);
}

// round 13
// speedup vs baseline: 1.3314x; 1.1918x over previous
#include <cuda_runtime.h>
#include <cuda_fp16.h>
#include <cstdint>

#define NN    4096
#define DD    128
#define TWO_N 8192
#define ZC    256
#define KSPLIT 4
#define KPER  (NN / KSPLIT)      // 1024 per CTA
#define KC    64
#define NCHC  (KPER / KC)        // 16 chunks per CTA
#define NCH_ALL (NN / KC)        // 64 chunks total
#define BSTG  16384              // B stage: 64x128 fp16
#define STG   17408              // B + 1KB mask
#define STAGES 4
#define SMEM_GEMM (STAGES * STG) // 69632 -> 2 CTAs/SM (139 KB)
#define SMEM_XWM  65536          // x tile 32K + W tile 32K

// ------------------------- device scratch -------------------------
__device__ __align__(16) unsigned g_maskT[(size_t)NCH_ALL * NN * 2]; // 2 MB [chunk][row][2w]
__device__ __align__(16) __half g_Zh[(size_t)NN * ZC];               // 2 MB [K][N]
__device__ __align__(16) float g_XW[(size_t)TWO_N * DD];             // 4 MB
__device__ __align__(16) float g_Yp[KSPLIT][(size_t)NN * ZC];        // 16 MB partials
__device__ float g_s[NN];
__device__ float g_stats[2 * DD];

// ------------------------- PTX helpers ----------------------------
__device__ __forceinline__ uint32_t smem_u32(const void* p) {
    uint32_t a;
    asm("{ .reg .u64 t; cvta.to.shared.u64 t, %1; cvt.u32.u64 %0, t; }" : "=r"(a) : "l"(p));
    return a;
}
#define CP16(dst, src) asm volatile("cp.async.cg.shared.global [%0], [%1], 16;" :: "r"(dst), "l"(src))
#define CP8(dst, src)  asm volatile("cp.async.ca.shared.global [%0], [%1], 8;"  :: "r"(dst), "l"(src))
#define CP_COMMIT()    asm volatile("cp.async.commit_group;" ::: "memory")
#define CP_WAITN(n)    asm volatile("cp.async.wait_group %0;" :: "n"(n) : "memory")

#define LDSM4(r, a)  asm volatile("ldmatrix.sync.aligned.m8n8.x4.shared.b16 {%0,%1,%2,%3}, [%4];" \
    : "=r"((r)[0]),"=r"((r)[1]),"=r"((r)[2]),"=r"((r)[3]) : "r"(a))
#define LDSM4T(r, a) asm volatile("ldmatrix.sync.aligned.m8n8.x4.trans.shared.b16 {%0,%1,%2,%3}, [%4];" \
    : "=r"((r)[0]),"=r"((r)[1]),"=r"((r)[2]),"=r"((r)[3]) : "r"(a))

#define MMA(d, a, b0_, b1_) asm volatile( \
    "mma.sync.aligned.m16n8k16.row.col.f32.f16.f16.f32 " \
    "{%0,%1,%2,%3},{%4,%5,%6,%7},{%8,%9},{%0,%1,%2,%3};" \
    : "+f"((d)[0]),"+f"((d)[1]),"+f"((d)[2]),"+f"((d)[3]) \
    : "r"((a)[0]),"r"((a)[1]),"r"((a)[2]),"r"((a)[3]), "r"(b0_), "r"(b1_))

// 2 bits -> packed fp16x2 (bit0 -> low half, bit1 -> high half), 1.0 or 0.0
__device__ __forceinline__ uint32_t lut2(unsigned e) {
    return ((e & 1u) ? 0x3C00u : 0u) | ((e & 2u) ? 0x3C000000u : 0u);
}
__device__ __forceinline__ uint32_t pack_h2(float a, float b) {
    return (uint32_t)__half_as_ushort(__float2half_rn(a))
         | ((uint32_t)__half_as_ushort(__float2half_rn(b)) << 16);
}

// ---------------------------------------------------------------------------
// K1: binarize A -> transposed bitmask [chunk][row][2 words]; rowsum -> s.
// ---------------------------------------------------------------------------
__global__ void k_prep(const float* __restrict__ A) {
    int row = blockIdx.x, t = threadIdx.x, w = t >> 5, l = t & 31;
    __shared__ int scnt[4];
    if (row == 0 && t < 128) { g_stats[t] = 0.0f; g_stats[128 + t] = 0.0f; }
    const float* ar = A + (size_t)row * NN;
    int cnt = 0;
    #pragma unroll 4
    for (int it = 0; it < 32; ++it) {
        float v = ar[it * 128 + t];
        bool b = (v > 0.0f);
        unsigned bal = __ballot_sync(0xffffffffu, b);
        cnt += b ? 1 : 0;
        if (l == 0) {
            int W = it * 4 + w;                      // 32-col word index 0..127
            g_maskT[((size_t)(W >> 1) * NN + row) * 2 + (W & 1)] = bal;
        }
    }
    #pragma unroll
    for (int o = 16; o; o >>= 1) cnt += __shfl_down_sync(0xffffffffu, cnt, o);
    if (l == 0) scnt[w] = cnt;
    __syncthreads();
    if (t == 0)
        g_s[row] = rsqrtf((float)(scnt[0] + scnt[1] + scnt[2] + scnt[3] + 1));
}

// ---------------------------------------------------------------------------
// K2: xw = x@W on tensor cores, fused Z build. grid 64 CTAs x 256 thr.
// CTA: 128 output rows. x, W converted to fp16 in smem (gemm-convention
// chunk swizzle: 256B rows, 16B chunk ch stored at (ch ^ (row&7))).
// 8 warps, warp tile 16x128 (r10-proven fragment layout). Epilogue writes
// XW fp32 (diag path) and Zh = fp16(s * xw) (GEMM B operand).
// ---------------------------------------------------------------------------
__global__ void __launch_bounds__(256) k_xwm(const float* __restrict__ x,
                                             const float* __restrict__ W) {
    extern __shared__ char smem[];
    uint32_t sb = smem_u32(smem);          // [0,32768) x-tile, [32768,65536) W-tile
    int t = threadIdx.x, wid = t >> 5, lid = t & 31;
    int rbase = blockIdx.x * 128;

    // convert x rows rbase..rbase+127 to fp16 smem
    #pragma unroll
    for (int p = 0; p < 16; ++p) {
        int idx = t + p * 256;             // (r, k4): r=idx>>5, k4=idx&31
        int r = idx >> 5, k4 = idx & 31;
        float4 v = *(const float4*)&x[(size_t)(rbase + r) * DD + k4 * 4];
        uint2 pk = make_uint2(pack_h2(v.x, v.y), pack_h2(v.z, v.w));
        uint32_t off = (uint32_t)(r * 256 + (((k4 >> 1) ^ (r & 7)) << 4) + (k4 & 1) * 8);
        *(uint2*)(smem + off) = pk;
    }
    // convert W (rows k, cols n) to fp16 smem
    #pragma unroll
    for (int p = 0; p < 16; ++p) {
        int idx = t + p * 256;
        int k = idx >> 5, n4 = idx & 31;
        float4 v = *(const float4*)&W[(size_t)k * DD + n4 * 4];
        uint2 pk = make_uint2(pack_h2(v.x, v.y), pack_h2(v.z, v.w));
        uint32_t off = (uint32_t)(32768 + k * 256 + (((n4 >> 1) ^ (k & 7)) << 4) + (n4 & 1) * 8);
        *(uint2*)(smem + off) = pk;
    }
    __syncthreads();

    int m0 = wid * 16;
    float acc[16][4];
    #pragma unroll
    for (int nj = 0; nj < 16; ++nj)
        #pragma unroll
        for (int q = 0; q < 4; ++q) acc[nj][q] = 0.0f;

    #pragma unroll
    for (int kk = 0; kk < 8; ++kk) {
        uint32_t af[4];
        int arow = m0 + (lid & 15);
        int ach  = kk * 2 + (lid >> 4);
        LDSM4(af, sb + arow * 256 + ((ach ^ (arow & 7)) << 4));
        int kb = kk * 16 + (lid & 15);
        int cb = lid >> 4;
        #pragma unroll
        for (int g = 0; g < 4; ++g) {
            uint32_t bf[4][2];
            #pragma unroll
            for (int np = 0; np < 2; ++np) {
                int ch = g * 4 + np * 2 + cb;
                uint32_t r4[4];
                LDSM4T(r4, sb + 32768 + kb * 256 + ((ch ^ (kb & 7)) << 4));
                bf[np*2][0]=r4[0]; bf[np*2][1]=r4[1];
                bf[np*2+1][0]=r4[2]; bf[np*2+1][1]=r4[3];
            }
            #pragma unroll
            for (int nj = 0; nj < 4; ++nj)
                MMA(acc[g * 4 + nj], af, bf[nj][0], bf[nj][1]);
        }
    }

    // epilogue: rows gr0 = rbase+m0+grp, gr1 = gr0+8; cols nj*8+qp*2
    int grp = lid >> 2, qp = lid & 3;
    int gr0 = rbase + m0 + grp;
    int gr1 = gr0 + 8;
    int top0 = (gr0 < NN);
    int j0 = top0 ? gr0 : (gr0 - NN);
    int j1 = top0 ? gr1 : (gr1 - NN);
    float s0 = g_s[j0], s1 = g_s[j1];
    int cof = top0 ? 0 : DD;
    #pragma unroll
    for (int nj = 0; nj < 16; ++nj) {
        int c = nj * 8 + qp * 2;
        *(float2*)&g_XW[(size_t)gr0 * DD + c] = make_float2(acc[nj][0], acc[nj][1]);
        *(float2*)&g_XW[(size_t)gr1 * DD + c] = make_float2(acc[nj][2], acc[nj][3]);
        *(uint32_t*)&g_Zh[(size_t)j0 * ZC + cof + c] = pack_h2(s0 * acc[nj][0], s0 * acc[nj][1]);
        *(uint32_t*)&g_Zh[(size_t)j1 * ZC + cof + c] = pack_h2(s1 * acc[nj][2], s1 * acc[nj][3]);
    }
}

// ---------------------------------------------------------------------------
// K3: GEMM partials. grid (32, 2, 4): CTA 128x128, K-split/4 on grid.z.
// 8 warps, warp tile 16x128 (one mask expansion per kk feeds 16 MMAs).
// 4-stage cp.async, one barrier per chunk, 2 CTAs/SM.
// ---------------------------------------------------------------------------
__global__ void __launch_bounds__(256, 2) k_gemm() {
    extern __shared__ char smem[];
    uint32_t sb = smem_u32(smem);
    int t = threadIdx.x, wid = t >> 5, lid = t & 31;
    int m0 = wid * 16;
    int mbase = blockIdx.x * 128;
    int nbg   = blockIdx.y * 128;
    const __half* Bg = g_Zh + (size_t)(blockIdx.z * KPER) * ZC + nbg;
    const unsigned* Mg = g_maskT + ((size_t)(blockIdx.z * NCHC) * NN + mbase) * 2;

    auto issue = [&](int c) {
        if (c < NCHC) {
            uint32_t sa = sb + (c % STAGES) * STG;
            #pragma unroll
            for (int p = 0; p < 4; ++p) {            // B: 64x128 fp16, 256B rows
                int idx = t + p * 256;
                int k = idx >> 4, ch = idx & 15;
                uint32_t off = k * 256 + ((ch ^ (k & 7)) << 4);
                CP16(sa + off, (const char*)(Bg + (size_t)(c * KC + k) * ZC + ch * 8));
            }
            if (t < 128)                              // mask: 128 rows x 8B
                CP8(sa + BSTG + t * 8, (const char*)(Mg + (size_t)c * NN * 2 + t * 2));
        }
        CP_COMMIT();
    };

    float acc[16][4];
    #pragma unroll
    for (int nj = 0; nj < 16; ++nj)
        #pragma unroll
        for (int q = 0; q < 4; ++q) acc[nj][q] = 0.0f;

    issue(0); issue(1); issue(2);

    int ra = lid >> 2;
    int c0 = (lid & 3) * 2;

    for (int c = 0; c < NCHC; ++c) {
        CP_WAITN(2);                 // chunk c resident (<=2 groups pending)
        __syncthreads();             // all warps done with stage (c-1)%4
        issue(c + 3);                // refills stage (c+3)%4 == (c-1)%4
        uint32_t sa = sb + (c % STAGES) * STG;
        const uint2* maskS = (const uint2*)(smem + (c % STAGES) * STG + BSTG);

        uint2 mw0 = maskS[m0 + ra];      // row m0+ra of my strip
        uint2 mw1 = maskS[m0 + ra + 8];  // row m0+ra+8

        #pragma unroll
        for (int kk = 0; kk < 4; ++kk) {
            int kb = kk * 16 + (lid & 15);
            int cb = lid >> 4;
            int sh = ((kk & 1) << 4) + c0;
            unsigned ta = ((kk < 2) ? mw0.x : mw0.y) >> sh;
            unsigned tb = ((kk < 2) ? mw1.x : mw1.y) >> sh;
            uint32_t af[4];
            af[0] = lut2(ta & 3u);           // (ra,   c0..c0+1)
            af[1] = lut2(tb & 3u);           // (ra+8, c0..c0+1)
            af[2] = lut2((ta >> 8) & 3u);    // (ra,   c0+8..c0+9)
            af[3] = lut2((tb >> 8) & 3u);    // (ra+8, c0+8..c0+9)
            #pragma unroll
            for (int g = 0; g < 4; ++g) {            // 4 groups of 32 cols
                uint32_t bf[4][2];
                #pragma unroll
                for (int np = 0; np < 2; ++np) {
                    int ch = g * 4 + np * 2 + cb;    // 16B column-chunk index
                    uint32_t r4[4];
                    LDSM4T(r4, sa + kb * 256 + ((ch ^ (kb & 7)) << 4));
                    bf[np*2][0]=r4[0]; bf[np*2][1]=r4[1];
                    bf[np*2+1][0]=r4[2]; bf[np*2+1][1]=r4[3];
                }
                #pragma unroll
                for (int nj = 0; nj < 4; ++nj)
                    MMA(acc[g * 4 + nj], af, bf[nj][0], bf[nj][1]);
            }
        }
    }

    // write partial tile (16 rows x 128 cols per warp)
    float* Yp = g_Yp[blockIdx.z];
    int grp = lid >> 2, qp = lid & 3;
    int r0 = mbase + m0 + grp;
    int r1 = r0 + 8;
    #pragma unroll
    for (int nj = 0; nj < 16; ++nj) {
        int cc = nbg + nj * 8 + qp * 2;
        *(float2*)&Yp[(size_t)r0 * ZC + cc] = make_float2(acc[nj][0], acc[nj][1]);
        *(float2*)&Yp[(size_t)r1 * ZC + cc] = make_float2(acc[nj][2], acc[nj][3]);
    }
}

// ---------------------------------------------------------------------------
// K4: epilogue (proven config). grid 256 x 256, 4 slots/thread.
// ---------------------------------------------------------------------------
__global__ void k_epi(float* __restrict__ out) {
    __shared__ float sstat[2 * DD];
    int t = threadIdx.x;
    sstat[t] = 0.0f;
    __syncthreads();
    int base = blockIdx.x * 256 + t;            // 4 slots/thread, stride 65536
    int C = (base & 63) * 4;                    // column invariant across slots
    float lsum[4] = {0.f, 0.f, 0.f, 0.f};
    float lsq[4]  = {0.f, 0.f, 0.f, 0.f};
    int oc = (C < DD) ? C : (C - DD);
    #pragma unroll
    for (int sIt = 0; sIt < 4; ++sIt) {
        int slot = base + sIt * 65536;
        int i = slot >> 6;
        float4 y = *(const float4*)&g_Yp[0][(size_t)i * ZC + C];
        #pragma unroll
        for (int z = 1; z < KSPLIT; ++z) {
            float4 p = *(const float4*)&g_Yp[z][(size_t)i * ZC + C];
            y.x += p.x; y.y += p.y; y.z += p.z; y.w += p.w;
        }
        float s = g_s[i], s2 = s * s;
        int orow, drow;
        if (C < DD) { orow = i; drow = NN + i; }
        else        { orow = NN + i; drow = i; }
        float4 d = *(const float4*)&g_XW[(size_t)drow * DD + oc];
        float4 h;
        h.x = s * y.x + s2 * d.x; h.y = s * y.y + s2 * d.y;
        h.z = s * y.z + s2 * d.z; h.w = s * y.w + s2 * d.w;
        *(float4*)&out[(size_t)orow * DD + oc] = h;
        lsum[0] += h.x; lsum[1] += h.y; lsum[2] += h.z; lsum[3] += h.w;
        lsq[0] += h.x * h.x; lsq[1] += h.y * h.y; lsq[2] += h.z * h.z; lsq[3] += h.w * h.w;
    }
    #pragma unroll
    for (int q = 0; q < 4; ++q) {
        atomicAdd(&sstat[oc + q], lsum[q]);
        atomicAdd(&sstat[DD + oc + q], lsq[q]);
    }
    __syncthreads();
    atomicAdd(&g_stats[t], sstat[t]);
}

// ---------------------------------------------------------------------------
// K5: finalize BatchNorm (biased var) + ReLU, float4 per thread.
// ---------------------------------------------------------------------------
__global__ void k_bn(float* __restrict__ out,
                     const float* __restrict__ gamma,
                     const float* __restrict__ beta) {
    __shared__ float sscale[DD], sshift[DD];
    int t = threadIdx.x;
    if (t < DD) {
        float mean = g_stats[t] * (1.0f / (float)TWO_N);
        float var  = g_stats[DD + t] * (1.0f / (float)TWO_N) - mean * mean;
        float inv  = rsqrtf(var + 1e-5f);
        float g = gamma[t];
        sscale[t] = inv * g;
        sshift[t] = beta[t] - mean * inv * g;
    }
    __syncthreads();
    int idx = (blockIdx.x * 256 + t) * 4;
    int c = idx & (DD - 1);
    float4 v = *(float4*)&out[idx];
    v.x = fmaxf(v.x * sscale[c]     + sshift[c],     0.0f);
    v.y = fmaxf(v.y * sscale[c + 1] + sshift[c + 1], 0.0f);
    v.z = fmaxf(v.z * sscale[c + 2] + sshift[c + 2], 0.0f);
    v.w = fmaxf(v.w * sscale[c + 3] + sshift[c + 3], 0.0f);
    *(float4*)&out[idx] = v;
}

// ---------------------------------------------------------------------------
extern "C" void kernel_launch(void* const* d_in, const int* in_sizes, int n_in,
                              void* d_out, int out_size) {
    const float* x     = (const float*)d_in[0];   // [8192, 128]
    const float* A     = (const float*)d_in[1];   // [4096, 4096]
    const float* Wm    = (const float*)d_in[2];   // [128, 128]
    const float* gamma = (const float*)d_in[3];   // [128]
    const float* beta  = (const float*)d_in[4];   // [128]
    float* out = (float*)d_out;                   // [8192, 128]

    cudaFuncSetAttribute(k_gemm, cudaFuncAttributeMaxDynamicSharedMemorySize, SMEM_GEMM);
    cudaFuncSetAttribute(k_xwm,  cudaFuncAttributeMaxDynamicSharedMemorySize, SMEM_XWM);

    k_prep<<<NN, 128>>>(A);
    k_xwm <<<TWO_N / 128, 256, SMEM_XWM>>>(x, Wm);
    dim3 gg(NN / 128, 2, KSPLIT);
    k_gemm<<<gg, 256, SMEM_GEMM>>>();
    k_epi <<<256, 256>>>(out);
    k_bn  <<<(TWO_N * DD) / 1024, 256>>>(out, gamma, beta);
}